// round 15
// baseline (speedup 1.0000x reference)
#include <cuda_runtime.h>
#include <cuda_fp16.h>
#include <math.h>
#include <stdint.h>

#define BB   2
#define TT   4096
#define CC   512
#define HH   8
#define DD   64
#define MEMW 256

#define M_TOT (BB*TT)     // 8192
#define QKVN  (3*CC)      // 1536

#define XN  (M_TOT*CC)
#define WAN (QKVN*CC)
#define WPN (CC*CC)

// scratch (allocation-free contract: device globals) — fp16
__device__ __half g_qkv[BB*TT*3*CC];
__device__ __half g_y[BB*TT*CC];
__device__ __half g_xc[XN];
__device__ __half g_wac[WAN];
__device__ __half g_wpc[WPN];

// ===========================================================================
// helpers
// ===========================================================================
__device__ __forceinline__ uint32_t smem_u32(const void* p) {
    uint32_t a;
    asm("{ .reg .u64 t; cvta.to.shared.u64 t, %1; cvt.u32.u64 %0, t; }"
        : "=r"(a) : "l"(p));
    return a;
}
#define SW128(off) ((off) ^ (((off) >> 3) & 0x70))

#define LDSM_X4(r0, r1, r2, r3, addr) \
    asm volatile("ldmatrix.sync.aligned.m8n8.x4.shared.b16 {%0,%1,%2,%3}, [%4];" \
                 : "=r"(r0), "=r"(r1), "=r"(r2), "=r"(r3) : "r"(addr))

#define LDSM_X4T(r0, r1, r2, r3, addr) \
    asm volatile("ldmatrix.sync.aligned.m8n8.x4.trans.shared.b16 {%0,%1,%2,%3}, [%4];" \
                 : "=r"(r0), "=r"(r1), "=r"(r2), "=r"(r3) : "r"(addr))

#define MMA_F16(c, a0, a1, a2, a3, b0, b1) \
    asm volatile("mma.sync.aligned.m16n8k16.row.col.f32.f16.f16.f32 " \
                 "{%0,%1,%2,%3}, {%4,%5,%6,%7}, {%8,%9}, {%0,%1,%2,%3};" \
                 : "+f"((c)[0]), "+f"((c)[1]), "+f"((c)[2]), "+f"((c)[3]) \
                 : "r"(a0), "r"(a1), "r"(a2), "r"(a3), "r"(b0), "r"(b1))

__device__ __forceinline__ void cp_async16(uint32_t s, const void* g) {
    asm volatile("cp.async.cg.shared.global [%0], [%1], 16;"
                 :: "r"(s), "l"(__cvta_generic_to_global(g)));
}
__device__ __forceinline__ void cp_async16_z(uint32_t s, const void* g, int sz) {
    asm volatile("cp.async.cg.shared.global [%0], [%1], 16, %2;"
                 :: "r"(s), "l"(__cvta_generic_to_global(g)), "r"(sz));
}
#define CP_COMMIT() asm volatile("cp.async.commit_group;" ::: "memory")
#define CP_WAIT(n)  asm volatile("cp.async.wait_group %0;" :: "n"(n) : "memory")
#define BAR_PAIR(id) asm volatile("bar.sync %0, 64;" :: "r"(id) : "memory")

__device__ __forceinline__ uint32_t packh2(float a, float b) {
    __half2 h = __floats2half2_rn(a, b);
    return *(uint32_t*)&h;
}
__device__ __forceinline__ float ex2f(float x) {
    float r;
    asm("ex2.approx.f32 %0, %1;" : "=f"(r) : "f"(x));
    return r;
}

// scores pre-scaled by 1/sqrt(d) * log2(e) so softmax uses raw ex2
#define SCL 0.18033688011112042f

// ===========================================================================
// pre-convert: fp32 -> fp16 for x, w_attn, w_proj  (unchanged)
// ===========================================================================
__global__ __launch_bounds__(256) void convert_kernel(const float* __restrict__ x,
                                                      const float* __restrict__ wa,
                                                      const float* __restrict__ wp) {
    const int i8 = blockIdx.x * 256 + threadIdx.x;
    const int total8 = (XN + WAN + WPN) / 8;
    if (i8 >= total8) return;
    const float* src;
    __half* dst;
    int j = i8;
    if (j < XN / 8)                   { src = x;  dst = g_xc; }
    else if ((j -= XN / 8) < WAN / 8) { src = wa; dst = g_wac; }
    else                              { j -= WAN / 8; src = wp; dst = g_wpc; }
    float4 v0 = ((const float4*)src)[j * 2];
    float4 v1 = ((const float4*)src)[j * 2 + 1];
    uint4 o = make_uint4(packh2(v0.x, v0.y), packh2(v0.z, v0.w),
                         packh2(v1.x, v1.y), packh2(v1.z, v1.w));
    ((uint4*)dst)[j] = o;
}

// ===========================================================================
// fp16 mma.sync GEMM (NT): C[m,n] = sum_k A[m,k]*W[n,k]
// R15: CTA tile 128x64, warp tile 32x32 (8 warps: 4m x 2n), BK=64,
// 3-stage cp.async, 3 CTA/SM target (regs<=84, smem 72KB).
// ===========================================================================
#define GBM 128
#define GBN 64
#define GBK 64
#define STAGES 3
#define A_TB (GBM * 128)                // 16384
#define B_TB (GBN * 128)                // 8192
#define STG_B (A_TB + B_TB)             // 24576
#define GEMM_SMEM (STAGES * STG_B)      // 73728

__global__ __launch_bounds__(256, 3) void gemm_fp16(const __half* __restrict__ A,
                                                    const __half* __restrict__ W,
                                                    void* __restrict__ CoutV,
                                                    int M, int N, int K,
                                                    int round_out, int mbase) {
    extern __shared__ char dynsm[];
    const uint32_t smb = smem_u32(dynsm);

    const int tid  = threadIdx.x;
    const int lane = tid & 31;
    const int wid  = tid >> 5;
    const int wm   = wid & 3;           // 32-row slice
    const int wn   = wid >> 2;          // 32-col slice
    const int m0 = mbase + blockIdx.y * GBM;
    const int n0 = blockIdx.x * GBN;

    const int crow = tid >> 3;          // 0..31
    const int cc   = tid & 7;
    const uint32_t cbyte = SW128((uint32_t)(crow * 128 + cc * 16));

    const int nk = K / GBK;

    auto issue_copy = [&](int kt) {
        const int s = kt % STAGES;
        const int k0 = kt * GBK;
        const uint32_t sa = smb + s * STG_B;
        const uint32_t sb = sa + A_TB;
        #pragma unroll
        for (int it = 0; it < 4; it++) {            // A: 128 rows
            const int row = crow + it * 32;
            cp_async16(sa + cbyte + it * 32 * 128,
                       &A[(size_t)(m0 + row) * K + k0 + cc * 8]);
        }
        #pragma unroll
        for (int it = 0; it < 2; it++) {            // B: 64 rows
            const int row = crow + it * 32;
            cp_async16(sb + cbyte + it * 32 * 128,
                       &W[(size_t)(n0 + row) * K + k0 + cc * 8]);
        }
    };

    float acc[2][4][4];
    #pragma unroll
    for (int i = 0; i < 2; i++)
        #pragma unroll
        for (int j = 0; j < 4; j++)
            #pragma unroll
            for (int k = 0; k < 4; k++) acc[i][j][k] = 0.f;

    const int a_row = (lane & 7) + ((lane >> 3) & 1) * 8;
    const int a_col = (lane >> 4) * 16;
    const int b_row = (lane & 7) + (lane >> 4) * 8;
    const int b_col = ((lane >> 3) & 1) * 16;

    #pragma unroll
    for (int s = 0; s < STAGES - 1; s++) {
        issue_copy(s);
        CP_COMMIT();
    }

    for (int kt = 0; kt < nk; kt++) {
        CP_WAIT(STAGES - 2);
        __syncthreads();
        if (kt + STAGES - 1 < nk) issue_copy(kt + STAGES - 1);
        CP_COMMIT();

        const uint32_t sa = smb + (kt % STAGES) * STG_B;
        const uint32_t sb = sa + A_TB;

        #pragma unroll
        for (int ks = 0; ks < 4; ks++) {            // 4 x k16
            uint32_t a[2][4];
            #pragma unroll
            for (int fm = 0; fm < 2; fm++) {
                int row = wm * 32 + fm * 16 + a_row;
                LDSM_X4(a[fm][0], a[fm][1], a[fm][2], a[fm][3],
                        sa + SW128((uint32_t)(row * 128 + ks * 32 + a_col)));
            }
            uint32_t b[2][4];
            #pragma unroll
            for (int bg = 0; bg < 2; bg++) {
                int row = wn * 32 + bg * 16 + b_row;
                LDSM_X4(b[bg][0], b[bg][1], b[bg][2], b[bg][3],
                        sb + SW128((uint32_t)(row * 128 + ks * 32 + b_col)));
            }
            #pragma unroll
            for (int fm = 0; fm < 2; fm++)
                #pragma unroll
                for (int fn = 0; fn < 4; fn++) {
                    const int bg = fn >> 1;
                    if (fn & 1) {
                        MMA_F16(acc[fm][fn], a[fm][0], a[fm][1], a[fm][2], a[fm][3],
                                b[bg][2], b[bg][3]);
                    } else {
                        MMA_F16(acc[fm][fn], a[fm][0], a[fm][1], a[fm][2], a[fm][3],
                                b[bg][0], b[bg][1]);
                    }
                }
        }
    }
    __syncthreads();

    const int g = lane >> 2;
    const int cpair = (lane & 3) * 2;
    if (round_out) {
        __half* Ch = (__half*)CoutV;
        #pragma unroll
        for (int fm = 0; fm < 2; fm++)
            #pragma unroll
            for (int fn = 0; fn < 4; fn++) {
                int r = m0 + wm * 32 + fm * 16 + g;
                int c = n0 + wn * 32 + fn * 8 + cpair;
                *(uint32_t*)&Ch[(size_t)r * N + c] =
                    packh2(acc[fm][fn][0], acc[fm][fn][1]);
                *(uint32_t*)&Ch[(size_t)(r + 8) * N + c] =
                    packh2(acc[fm][fn][2], acc[fm][fn][3]);
            }
    } else {
        float* Cf = (float*)CoutV;
        #pragma unroll
        for (int fm = 0; fm < 2; fm++)
            #pragma unroll
            for (int fn = 0; fn < 4; fn++) {
                int r = m0 + wm * 32 + fm * 16 + g;
                int c = n0 + wn * 32 + fn * 8 + cpair;
                *(float2*)&Cf[(size_t)r * N + c] =
                    make_float2(acc[fm][fn][0], acc[fm][fn][1]);
                *(float2*)&Cf[(size_t)(r + 8) * N + c] =
                    make_float2(acc[fm][fn][2], acc[fm][fn][3]);
            }
    }
}

// ===========================================================================
// Flash sliding-window attention v5 (unchanged from R14)
// ===========================================================================
#define QT 64
#define KT 64
#define NKT 5
#define OBP 72

#define AQ   0
#define AK   8192
#define AV   32768
#define AOB  57344
#define ASR  75776
#define ATTN_SMEM_BYTES 76288

__global__ __launch_bounds__(256, 2) void attn_flash(const __half* __restrict__ qkv,
                                                     __half* __restrict__ y,
                                                     int bfix) {
    extern __shared__ char shm[];
    float* Obuf = (float*)(shm + AOB);
    float* Sm   = (float*)(shm + ASR);
    float* Sl   = (float*)(shm + ASR) + 64;

    const int tid  = threadIdx.x;
    const int lane = tid & 31;
    const int wid  = tid >> 5;
    const int wm   = wid & 3;
    const int wn   = wid >> 2;
    const int q0 = blockIdx.x * QT;
    const int h  = blockIdx.y;
    const int b  = bfix;
    const int kstart = q0 - MEMW;
    const int kt0 = (q0 < MEMW) ? (MEMW - q0) / KT : 0;

    const __half* qbase = qkv + (size_t)b * TT * QKVN + h * DD;
    const __half* kbase = qbase + CC;
    const __half* vbase = qbase + 2 * CC;

    const uint32_t uQ = smem_u32(shm) + AQ;
    const uint32_t uK = smem_u32(shm) + AK;
    const uint32_t uV = smem_u32(shm) + AV;

    const int a_row = (lane & 7) + ((lane >> 3) & 1) * 8;
    const int a_col = (lane >> 4) * 16;
    const int b_row = (lane & 7) + (lane >> 4) * 8;
    const int b_col = ((lane >> 3) & 1) * 16;
    const int g  = lane >> 2;
    const int c2 = (lane & 3) * 2;
    const int r0 = wm * 16 + g;

    #pragma unroll
    for (int it = 0; it < 2; it++) {
        int idx = it * 256 + tid;
        int row = idx >> 3;
        int cc  = idx & 7;
        cp_async16(uQ + SW128((uint32_t)(row * 128 + cc * 16)),
                   &qbase[(size_t)(q0 + row) * QKVN + cc * 8]);
    }
    auto issue_kv = [&](int kt) {
        const uint32_t boff = (uint32_t)(kt % 3) * 8192;
        const int kb = kstart + kt * KT;
        #pragma unroll
        for (int it = 0; it < 2; it++) {
            int idx = it * 256 + tid;
            int row = idx >> 3;
            int cc  = idx & 7;
            int gk  = kb + row;
            uint32_t sw = SW128((uint32_t)(row * 128 + cc * 16));
            int ok = (gk >= 0) ? 16 : 0;
            const __half* ks = (gk >= 0) ? &kbase[(size_t)gk * QKVN + cc * 8] : kbase;
            const __half* vs = (gk >= 0) ? &vbase[(size_t)gk * QKVN + cc * 8] : vbase;
            cp_async16_z(uK + boff + sw, ks, ok);
            cp_async16_z(uV + boff + sw, vs, ok);
        }
    };
    issue_kv(kt0);
    CP_COMMIT();
    if (kt0 + 1 < NKT) {
        issue_kv(kt0 + 1);
        CP_COMMIT();
    }

    float m_old0 = -1e30f, m_old1 = -1e30f;
    float srun0 = 0.f, srun1 = 0.f;
    float oacc[8][4];
    #pragma unroll
    for (int i = 0; i < 8; i++)
        #pragma unroll
        for (int j = 0; j < 4; j++) oacc[i][j] = 0.f;

    for (int kt = kt0; kt < NKT; kt++) {
        if (kt + 1 < NKT) { CP_WAIT(1); } else { CP_WAIT(0); }
        __syncthreads();
        if (kt + 2 < NKT) { issue_kv(kt + 2); CP_COMMIT(); }

        const int kb = kstart + kt * KT;
        const uint32_t boff = (uint32_t)(kt % 3) * 8192;

        float acc[4][4];
        #pragma unroll
        for (int i = 0; i < 4; i++)
            #pragma unroll
            for (int j = 0; j < 4; j++) acc[i][j] = 0.f;

        #pragma unroll
        for (int ks = 0; ks < 4; ks++) {
            uint32_t a[4];
            {
                int row = wm * 16 + a_row;
                LDSM_X4(a[0], a[1], a[2], a[3],
                        uQ + SW128((uint32_t)(row * 128 + ks * 32 + a_col)));
            }
            uint32_t bf[2][4];
            #pragma unroll
            for (int g2 = 0; g2 < 2; g2++) {
                int row = wn * 32 + g2 * 16 + b_row;
                LDSM_X4(bf[g2][0], bf[g2][1], bf[g2][2], bf[g2][3],
                        uK + boff + SW128((uint32_t)(row * 128 + ks * 32 + b_col)));
            }
            #pragma unroll
            for (int fn = 0; fn < 4; fn++) {
                const int bg = fn >> 1;
                if (fn & 1) {
                    MMA_F16(acc[fn], a[0], a[1], a[2], a[3], bf[bg][2], bf[bg][3]);
                } else {
                    MMA_F16(acc[fn], a[0], a[1], a[2], a[3], bf[bg][0], bf[bg][1]);
                }
            }
        }

        float mx0 = -1e30f, mx1 = -1e30f;
        if (kt == 0 || kt == NKT - 1) {
            const int qi0 = q0 + r0;
            const int qi1 = qi0 + 8;
            #pragma unroll
            for (int fn = 0; fn < 4; fn++) {
                int c  = wn * 32 + fn * 8 + c2;
                int kj = kb + c;
                #pragma unroll
                for (int jj = 0; jj < 2; jj++) {
                    int k = kj + jj;
                    bool ok0 = (k <= qi0) && (qi0 - k <= MEMW);
                    bool ok1 = (k <= qi1) && (qi1 - k <= MEMW);
                    acc[fn][jj]     = ok0 ? acc[fn][jj]     * SCL : -1e30f;
                    acc[fn][2 + jj] = ok1 ? acc[fn][2 + jj] * SCL : -1e30f;
                    mx0 = fmaxf(mx0, acc[fn][jj]);
                    mx1 = fmaxf(mx1, acc[fn][2 + jj]);
                }
            }
        } else {
            #pragma unroll
            for (int fn = 0; fn < 4; fn++) {
                #pragma unroll
                for (int jj = 0; jj < 2; jj++) {
                    acc[fn][jj]     *= SCL;
                    acc[fn][2 + jj] *= SCL;
                    mx0 = fmaxf(mx0, acc[fn][jj]);
                    mx1 = fmaxf(mx1, acc[fn][2 + jj]);
                }
            }
        }
        mx0 = fmaxf(mx0, __shfl_xor_sync(0xFFFFFFFF, mx0, 1));
        mx0 = fmaxf(mx0, __shfl_xor_sync(0xFFFFFFFF, mx0, 2));
        mx1 = fmaxf(mx1, __shfl_xor_sync(0xFFFFFFFF, mx1, 1));
        mx1 = fmaxf(mx1, __shfl_xor_sync(0xFFFFFFFF, mx1, 2));

        float m0 = fmaxf(m_old0, mx0);
        float m1 = fmaxf(m_old1, mx1);
        float f0 = ex2f(m_old0 - m0);
        float f1 = ex2f(m_old1 - m1);
        m_old0 = m0;
        m_old1 = m1;

        uint32_t aP[2][4];
        float s0 = 0.f, s1 = 0.f;
        #pragma unroll
        for (int kk = 0; kk < 2; kk++) {
            float p00 = ex2f(acc[2*kk][0] - m0);
            float p01 = ex2f(acc[2*kk][1] - m0);
            float p02 = ex2f(acc[2*kk][2] - m1);
            float p03 = ex2f(acc[2*kk][3] - m1);
            float p10 = ex2f(acc[2*kk+1][0] - m0);
            float p11 = ex2f(acc[2*kk+1][1] - m0);
            float p12 = ex2f(acc[2*kk+1][2] - m1);
            float p13 = ex2f(acc[2*kk+1][3] - m1);
            aP[kk][0] = packh2(p00, p01);
            aP[kk][1] = packh2(p02, p03);
            aP[kk][2] = packh2(p10, p11);
            aP[kk][3] = packh2(p12, p13);
            s0 += p00 + p01 + p10 + p11;
            s1 += p02 + p03 + p12 + p13;
        }
        s0 += __shfl_xor_sync(0xFFFFFFFF, s0, 1);
        s0 += __shfl_xor_sync(0xFFFFFFFF, s0, 2);
        s1 += __shfl_xor_sync(0xFFFFFFFF, s1, 1);
        s1 += __shfl_xor_sync(0xFFFFFFFF, s1, 2);
        srun0 = srun0 * f0 + s0;
        srun1 = srun1 * f1 + s1;

        #pragma unroll
        for (int fn = 0; fn < 8; fn++) {
            oacc[fn][0] *= f0;
            oacc[fn][1] *= f0;
            oacc[fn][2] *= f1;
            oacc[fn][3] *= f1;
        }

        #pragma unroll
        for (int kk = 0; kk < 2; kk++) {
            uint32_t bf[4][4];
            #pragma unroll
            for (int g2 = 0; g2 < 4; g2++) {
                int row = wn * 32 + kk * 16 + (lane & 7) + ((lane >> 3) & 1) * 8;
                int bcol = g2 * 32 + (lane >> 4) * 16;
                LDSM_X4T(bf[g2][0], bf[g2][1], bf[g2][2], bf[g2][3],
                         uV + boff + SW128((uint32_t)(row * 128 + bcol)));
            }
            #pragma unroll
            for (int fn = 0; fn < 8; fn++) {
                const int bg = fn >> 1;
                if (fn & 1) {
                    MMA_F16(oacc[fn], aP[kk][0], aP[kk][1], aP[kk][2], aP[kk][3],
                            bf[bg][2], bf[bg][3]);
                } else {
                    MMA_F16(oacc[fn], aP[kk][0], aP[kk][1], aP[kk][2], aP[kk][3],
                            bf[bg][0], bf[bg][1]);
                }
            }
        }
    }

    if (wn == 1) {
        #pragma unroll
        for (int fn = 0; fn < 8; fn++) {
            int col = fn * 8 + c2;
            float* d0 = &Obuf[(size_t)r0 * OBP + col];
            float* d1 = &Obuf[(size_t)(r0 + 8) * OBP + col];
            d0[0] = oacc[fn][0]; d0[1] = oacc[fn][1];
            d1[0] = oacc[fn][2]; d1[1] = oacc[fn][3];
        }
        if ((lane & 3) == 0) {
            Sm[r0] = m_old0;  Sm[r0 + 8] = m_old1;
            Sl[r0] = srun0;   Sl[r0 + 8] = srun1;
        }
    }
    BAR_PAIR(wm + 1);
    if (wn == 0) {
        float mo0 = Sm[r0], mo1 = Sm[r0 + 8];
        float lo0 = Sl[r0], lo1 = Sl[r0 + 8];
        float mm0 = fmaxf(m_old0, mo0);
        float mm1 = fmaxf(m_old1, mo1);
        float as0 = ex2f(m_old0 - mm0), ao0 = ex2f(mo0 - mm0);
        float as1 = ex2f(m_old1 - mm1), ao1 = ex2f(mo1 - mm1);
        float inv0 = 1.0f / (srun0 * as0 + lo0 * ao0);
        float inv1 = 1.0f / (srun1 * as1 + lo1 * ao1);
        #pragma unroll
        for (int fn = 0; fn < 8; fn++) {
            int col = fn * 8 + c2;
            const float* s0p = &Obuf[(size_t)r0 * OBP + col];
            const float* s1p = &Obuf[(size_t)(r0 + 8) * OBP + col];
            __half* p0 = &y[(size_t)(b * TT + q0 + r0) * CC + h * DD + col];
            __half* p1 = &y[(size_t)(b * TT + q0 + r0 + 8) * CC + h * DD + col];
            *(uint32_t*)p0 = packh2((oacc[fn][0] * as0 + s0p[0] * ao0) * inv0,
                                    (oacc[fn][1] * as0 + s0p[1] * ao0) * inv0);
            *(uint32_t*)p1 = packh2((oacc[fn][2] * as1 + s1p[0] * ao1) * inv1,
                                    (oacc[fn][3] * as1 + s1p[1] * ao1) * inv1);
        }
    }
}

// ===========================================================================
// launcher: 2-stream batch pipeline (R14 schedule; GEMM grids use GBN=64)
// ===========================================================================
extern "C" void kernel_launch(void* const* d_in, const int* in_sizes, int n_in,
                              void* d_out, int out_size) {
    const float* x      = (const float*)d_in[0];
    const float* w_attn = (const float*)d_in[1];
    const float* w_proj = (const float*)d_in[2];
    float* out = (float*)d_out;

    __half *qkv = nullptr, *yb = nullptr, *xc = nullptr, *wac = nullptr, *wpc = nullptr;
    cudaGetSymbolAddress((void**)&qkv, g_qkv);
    cudaGetSymbolAddress((void**)&yb,  g_y);
    cudaGetSymbolAddress((void**)&xc,  g_xc);
    cudaGetSymbolAddress((void**)&wac, g_wac);
    cudaGetSymbolAddress((void**)&wpc, g_wpc);

    cudaFuncSetAttribute(attn_flash,
                         cudaFuncAttributeMaxDynamicSharedMemorySize, ATTN_SMEM_BYTES);
    cudaFuncSetAttribute(gemm_fp16,
                         cudaFuncAttributeMaxDynamicSharedMemorySize, GEMM_SMEM);

    cudaStream_t s1;
    cudaStreamCreateWithFlags(&s1, cudaStreamNonBlocking);
    cudaEvent_t evQ0, evJoin;
    cudaEventCreateWithFlags(&evQ0,  cudaEventDisableTiming);
    cudaEventCreateWithFlags(&evJoin, cudaEventDisableTiming);

    const int MH = M_TOT / 2;

    {
        int total8 = (XN + WAN + WPN) / 8;
        convert_kernel<<<(total8 + 255) / 256, 256, 0, 0>>>(x, w_attn, w_proj);
    }
    {
        dim3 grid(QKVN / GBN, MH / GBM);
        gemm_fp16<<<grid, 256, GEMM_SMEM, 0>>>(xc, wac, qkv, M_TOT, QKVN, CC, 1, 0);
    }
    cudaEventRecord(evQ0, 0);
    cudaStreamWaitEvent(s1, evQ0, 0);

    {
        dim3 grid(QKVN / GBN, MH / GBM);
        gemm_fp16<<<grid, 256, GEMM_SMEM, s1>>>(xc, wac, qkv, M_TOT, QKVN, CC, 1, MH);
    }
    {
        dim3 grid(TT / QT, HH);
        attn_flash<<<grid, 256, ATTN_SMEM_BYTES, 0>>>(qkv, yb, 0);
    }
    {
        dim3 grid(CC / GBN, MH / GBM);
        gemm_fp16<<<grid, 256, GEMM_SMEM, 0>>>(yb, wpc, out, M_TOT, CC, CC, 0, 0);
    }
    {
        dim3 grid(TT / QT, HH);
        attn_flash<<<grid, 256, ATTN_SMEM_BYTES, s1>>>(qkv, yb, 1);
    }
    {
        dim3 grid(CC / GBN, MH / GBM);
        gemm_fp16<<<grid, 256, GEMM_SMEM, s1>>>(yb, wpc, out, M_TOT, CC, CC, 0, MH);
    }

    cudaEventRecord(evJoin, s1);
    cudaStreamWaitEvent(0, evJoin, 0);
}

// round 16
// speedup vs baseline: 1.0270x; 1.0270x over previous
#include <cuda_runtime.h>
#include <cuda_fp16.h>
#include <math.h>
#include <stdint.h>

#define BB   2
#define TT   4096
#define CC   512
#define HH   8
#define DD   64
#define MEMW 256

#define M_TOT (BB*TT)     // 8192
#define QKVN  (3*CC)      // 1536

#define XN  (M_TOT*CC)
#define WAN (QKVN*CC)
#define WPN (CC*CC)

// scratch (allocation-free contract: device globals) — fp16
__device__ __half g_qkv[BB*TT*3*CC];
__device__ __half g_y[BB*TT*CC];
__device__ __half g_xc[XN];
__device__ __half g_wac[WAN];
__device__ __half g_wpc[WPN];

// ===========================================================================
// helpers
// ===========================================================================
__device__ __forceinline__ uint32_t smem_u32(const void* p) {
    uint32_t a;
    asm("{ .reg .u64 t; cvta.to.shared.u64 t, %1; cvt.u32.u64 %0, t; }"
        : "=r"(a) : "l"(p));
    return a;
}
#define SW128(off) ((off) ^ (((off) >> 3) & 0x70))

#define LDSM_X4(r0, r1, r2, r3, addr) \
    asm volatile("ldmatrix.sync.aligned.m8n8.x4.shared.b16 {%0,%1,%2,%3}, [%4];" \
                 : "=r"(r0), "=r"(r1), "=r"(r2), "=r"(r3) : "r"(addr))

#define LDSM_X4T(r0, r1, r2, r3, addr) \
    asm volatile("ldmatrix.sync.aligned.m8n8.x4.trans.shared.b16 {%0,%1,%2,%3}, [%4];" \
                 : "=r"(r0), "=r"(r1), "=r"(r2), "=r"(r3) : "r"(addr))

#define MMA_F16(c, a0, a1, a2, a3, b0, b1) \
    asm volatile("mma.sync.aligned.m16n8k16.row.col.f32.f16.f16.f32 " \
                 "{%0,%1,%2,%3}, {%4,%5,%6,%7}, {%8,%9}, {%0,%1,%2,%3};" \
                 : "+f"((c)[0]), "+f"((c)[1]), "+f"((c)[2]), "+f"((c)[3]) \
                 : "r"(a0), "r"(a1), "r"(a2), "r"(a3), "r"(b0), "r"(b1))

__device__ __forceinline__ void cp_async16(uint32_t s, const void* g) {
    asm volatile("cp.async.cg.shared.global [%0], [%1], 16;"
                 :: "r"(s), "l"(__cvta_generic_to_global(g)));
}
__device__ __forceinline__ void cp_async16_z(uint32_t s, const void* g, int sz) {
    asm volatile("cp.async.cg.shared.global [%0], [%1], 16, %2;"
                 :: "r"(s), "l"(__cvta_generic_to_global(g)), "r"(sz));
}
#define CP_COMMIT() asm volatile("cp.async.commit_group;" ::: "memory")
#define CP_WAIT(n)  asm volatile("cp.async.wait_group %0;" :: "n"(n) : "memory")
#define BAR_PAIR(id) asm volatile("bar.sync %0, 64;" :: "r"(id) : "memory")

__device__ __forceinline__ uint32_t packh2(float a, float b) {
    __half2 h = __floats2half2_rn(a, b);
    return *(uint32_t*)&h;
}
__device__ __forceinline__ float ex2f(float x) {
    float r;
    asm("ex2.approx.f32 %0, %1;" : "=f"(r) : "f"(x));
    return r;
}

// scores pre-scaled by 1/sqrt(d) * log2(e) so softmax uses raw ex2
#define SCL 0.18033688011112042f

// ===========================================================================
// pre-convert: fp32 -> fp16, split in two parts so the pipeline starts early.
// part 0: w_attn + w_proj + x[batch 0];  part 1: x[batch 1].
// ===========================================================================
#define P0_TOTAL8 ((WAN + WPN + XN/2) / 8)
#define P1_TOTAL8 ((XN/2) / 8)

__global__ __launch_bounds__(256) void convert_kernel(const float* __restrict__ x,
                                                      const float* __restrict__ wa,
                                                      const float* __restrict__ wp,
                                                      int part) {
    const int i8 = blockIdx.x * 256 + threadIdx.x;
    const float* src;
    __half* dst;
    int j = i8;
    if (part == 0) {
        if (i8 >= P0_TOTAL8) return;
        if (j < WAN / 8)                  { src = wa; dst = g_wac; }
        else if ((j -= WAN / 8) < WPN / 8){ src = wp; dst = g_wpc; }
        else                              { j -= WPN / 8; src = x; dst = g_xc; }
    } else {
        if (i8 >= P1_TOTAL8) return;
        src = x + (size_t)XN / 2;
        dst = g_xc + (size_t)XN / 2;
    }
    float4 v0 = ((const float4*)src)[j * 2];
    float4 v1 = ((const float4*)src)[j * 2 + 1];
    uint4 o = make_uint4(packh2(v0.x, v0.y), packh2(v0.z, v0.w),
                         packh2(v1.x, v1.y), packh2(v1.z, v1.w));
    ((uint4*)dst)[j] = o;
}

// ===========================================================================
// fp16 mma.sync GEMM (NT), templated CTA tile 128xNB.
// NB=128: warp tile 32x64, (256,2), 96KB smem  (R14 config — for QKV)
// NB=64 : warp tile 32x32, (256,3), 72KB smem  (R15 config — for proj)
// ===========================================================================
#define GBM 128
#define GBK 64
#define STAGES 3
#define A_TB (GBM * 128)                 // 16384

template<int NB>
__global__ __launch_bounds__(256, (NB == 128) ? 2 : 3)
void gemm_fp16(const __half* __restrict__ A,
               const __half* __restrict__ W,
               void* __restrict__ CoutV,
               int M, int N, int K, int round_out, int mbase) {
    constexpr int WN   = NB / 2;        // warp N tile
    constexpr int FNC  = WN / 8;        // fn count
    constexpr int NBG  = WN / 16;       // B ldsm groups
    constexpr int B_TB = NB * 128;
    constexpr int STG_B = A_TB + B_TB;

    extern __shared__ char dynsm[];
    const uint32_t smb = smem_u32(dynsm);

    const int tid  = threadIdx.x;
    const int lane = tid & 31;
    const int wid  = tid >> 5;
    const int wm   = wid & 3;
    const int wn   = wid >> 2;
    const int m0 = mbase + blockIdx.y * GBM;
    const int n0 = blockIdx.x * NB;

    const int crow = tid >> 3;
    const int cc   = tid & 7;
    const uint32_t cbyte = SW128((uint32_t)(crow * 128 + cc * 16));

    const int nk = K / GBK;

    auto issue_copy = [&](int kt) {
        const int s = kt % STAGES;
        const int k0 = kt * GBK;
        const uint32_t sa = smb + s * STG_B;
        const uint32_t sb = sa + A_TB;
        #pragma unroll
        for (int it = 0; it < 4; it++) {
            const int row = crow + it * 32;
            cp_async16(sa + cbyte + it * 32 * 128,
                       &A[(size_t)(m0 + row) * K + k0 + cc * 8]);
        }
        #pragma unroll
        for (int it = 0; it < NB / 32; it++) {
            const int row = crow + it * 32;
            cp_async16(sb + cbyte + it * 32 * 128,
                       &W[(size_t)(n0 + row) * K + k0 + cc * 8]);
        }
    };

    float acc[2][FNC][4];
    #pragma unroll
    for (int i = 0; i < 2; i++)
        #pragma unroll
        for (int j = 0; j < FNC; j++)
            #pragma unroll
            for (int k = 0; k < 4; k++) acc[i][j][k] = 0.f;

    const int a_row = (lane & 7) + ((lane >> 3) & 1) * 8;
    const int a_col = (lane >> 4) * 16;
    const int b_row = (lane & 7) + (lane >> 4) * 8;
    const int b_col = ((lane >> 3) & 1) * 16;

    #pragma unroll
    for (int s = 0; s < STAGES - 1; s++) {
        issue_copy(s);
        CP_COMMIT();
    }

    for (int kt = 0; kt < nk; kt++) {
        CP_WAIT(STAGES - 2);
        __syncthreads();
        if (kt + STAGES - 1 < nk) issue_copy(kt + STAGES - 1);
        CP_COMMIT();

        const uint32_t sa = smb + (kt % STAGES) * STG_B;
        const uint32_t sb = sa + A_TB;

        #pragma unroll
        for (int ks = 0; ks < 4; ks++) {
            uint32_t a[2][4];
            #pragma unroll
            for (int fm = 0; fm < 2; fm++) {
                int row = wm * 32 + fm * 16 + a_row;
                LDSM_X4(a[fm][0], a[fm][1], a[fm][2], a[fm][3],
                        sa + SW128((uint32_t)(row * 128 + ks * 32 + a_col)));
            }
            uint32_t b[NBG][4];
            #pragma unroll
            for (int bg = 0; bg < NBG; bg++) {
                int row = wn * WN + bg * 16 + b_row;
                LDSM_X4(b[bg][0], b[bg][1], b[bg][2], b[bg][3],
                        sb + SW128((uint32_t)(row * 128 + ks * 32 + b_col)));
            }
            #pragma unroll
            for (int fm = 0; fm < 2; fm++)
                #pragma unroll
                for (int fn = 0; fn < FNC; fn++) {
                    const int bg = fn >> 1;
                    if (fn & 1) {
                        MMA_F16(acc[fm][fn], a[fm][0], a[fm][1], a[fm][2], a[fm][3],
                                b[bg][2], b[bg][3]);
                    } else {
                        MMA_F16(acc[fm][fn], a[fm][0], a[fm][1], a[fm][2], a[fm][3],
                                b[bg][0], b[bg][1]);
                    }
                }
        }
    }
    __syncthreads();

    const int g = lane >> 2;
    const int cpair = (lane & 3) * 2;
    if (round_out) {
        __half* Ch = (__half*)CoutV;
        #pragma unroll
        for (int fm = 0; fm < 2; fm++)
            #pragma unroll
            for (int fn = 0; fn < FNC; fn++) {
                int r = m0 + wm * 32 + fm * 16 + g;
                int c = n0 + wn * WN + fn * 8 + cpair;
                *(uint32_t*)&Ch[(size_t)r * N + c] =
                    packh2(acc[fm][fn][0], acc[fm][fn][1]);
                *(uint32_t*)&Ch[(size_t)(r + 8) * N + c] =
                    packh2(acc[fm][fn][2], acc[fm][fn][3]);
            }
    } else {
        float* Cf = (float*)CoutV;
        #pragma unroll
        for (int fm = 0; fm < 2; fm++)
            #pragma unroll
            for (int fn = 0; fn < FNC; fn++) {
                int r = m0 + wm * 32 + fm * 16 + g;
                int c = n0 + wn * WN + fn * 8 + cpair;
                *(float2*)&Cf[(size_t)r * N + c] =
                    make_float2(acc[fm][fn][0], acc[fm][fn][1]);
                *(float2*)&Cf[(size_t)(r + 8) * N + c] =
                    make_float2(acc[fm][fn][2], acc[fm][fn][3]);
            }
    }
}

#define GEMM_SMEM_128 (STAGES * (A_TB + 128 * 128))   // 98304
#define GEMM_SMEM_64  (STAGES * (A_TB + 64 * 128))    // 73728

// ===========================================================================
// Flash sliding-window attention v5 (unchanged from R14)
// ===========================================================================
#define QT 64
#define KT 64
#define NKT 5
#define OBP 72

#define AQ   0
#define AK   8192
#define AV   32768
#define AOB  57344
#define ASR  75776
#define ATTN_SMEM_BYTES 76288

__global__ __launch_bounds__(256, 2) void attn_flash(const __half* __restrict__ qkv,
                                                     __half* __restrict__ y,
                                                     int bfix) {
    extern __shared__ char shm[];
    float* Obuf = (float*)(shm + AOB);
    float* Sm   = (float*)(shm + ASR);
    float* Sl   = (float*)(shm + ASR) + 64;

    const int tid  = threadIdx.x;
    const int lane = tid & 31;
    const int wid  = tid >> 5;
    const int wm   = wid & 3;
    const int wn   = wid >> 2;
    const int q0 = blockIdx.x * QT;
    const int h  = blockIdx.y;
    const int b  = bfix;
    const int kstart = q0 - MEMW;
    const int kt0 = (q0 < MEMW) ? (MEMW - q0) / KT : 0;

    const __half* qbase = qkv + (size_t)b * TT * QKVN + h * DD;
    const __half* kbase = qbase + CC;
    const __half* vbase = qbase + 2 * CC;

    const uint32_t uQ = smem_u32(shm) + AQ;
    const uint32_t uK = smem_u32(shm) + AK;
    const uint32_t uV = smem_u32(shm) + AV;

    const int a_row = (lane & 7) + ((lane >> 3) & 1) * 8;
    const int a_col = (lane >> 4) * 16;
    const int b_row = (lane & 7) + (lane >> 4) * 8;
    const int b_col = ((lane >> 3) & 1) * 16;
    const int g  = lane >> 2;
    const int c2 = (lane & 3) * 2;
    const int r0 = wm * 16 + g;

    #pragma unroll
    for (int it = 0; it < 2; it++) {
        int idx = it * 256 + tid;
        int row = idx >> 3;
        int cc  = idx & 7;
        cp_async16(uQ + SW128((uint32_t)(row * 128 + cc * 16)),
                   &qbase[(size_t)(q0 + row) * QKVN + cc * 8]);
    }
    auto issue_kv = [&](int kt) {
        const uint32_t boff = (uint32_t)(kt % 3) * 8192;
        const int kb = kstart + kt * KT;
        #pragma unroll
        for (int it = 0; it < 2; it++) {
            int idx = it * 256 + tid;
            int row = idx >> 3;
            int cc  = idx & 7;
            int gk  = kb + row;
            uint32_t sw = SW128((uint32_t)(row * 128 + cc * 16));
            int ok = (gk >= 0) ? 16 : 0;
            const __half* ks = (gk >= 0) ? &kbase[(size_t)gk * QKVN + cc * 8] : kbase;
            const __half* vs = (gk >= 0) ? &vbase[(size_t)gk * QKVN + cc * 8] : vbase;
            cp_async16_z(uK + boff + sw, ks, ok);
            cp_async16_z(uV + boff + sw, vs, ok);
        }
    };
    issue_kv(kt0);
    CP_COMMIT();
    if (kt0 + 1 < NKT) {
        issue_kv(kt0 + 1);
        CP_COMMIT();
    }

    float m_old0 = -1e30f, m_old1 = -1e30f;
    float srun0 = 0.f, srun1 = 0.f;
    float oacc[8][4];
    #pragma unroll
    for (int i = 0; i < 8; i++)
        #pragma unroll
        for (int j = 0; j < 4; j++) oacc[i][j] = 0.f;

    for (int kt = kt0; kt < NKT; kt++) {
        if (kt + 1 < NKT) { CP_WAIT(1); } else { CP_WAIT(0); }
        __syncthreads();
        if (kt + 2 < NKT) { issue_kv(kt + 2); CP_COMMIT(); }

        const int kb = kstart + kt * KT;
        const uint32_t boff = (uint32_t)(kt % 3) * 8192;

        float acc[4][4];
        #pragma unroll
        for (int i = 0; i < 4; i++)
            #pragma unroll
            for (int j = 0; j < 4; j++) acc[i][j] = 0.f;

        #pragma unroll
        for (int ks = 0; ks < 4; ks++) {
            uint32_t a[4];
            {
                int row = wm * 16 + a_row;
                LDSM_X4(a[0], a[1], a[2], a[3],
                        uQ + SW128((uint32_t)(row * 128 + ks * 32 + a_col)));
            }
            uint32_t bf[2][4];
            #pragma unroll
            for (int g2 = 0; g2 < 2; g2++) {
                int row = wn * 32 + g2 * 16 + b_row;
                LDSM_X4(bf[g2][0], bf[g2][1], bf[g2][2], bf[g2][3],
                        uK + boff + SW128((uint32_t)(row * 128 + ks * 32 + b_col)));
            }
            #pragma unroll
            for (int fn = 0; fn < 4; fn++) {
                const int bg = fn >> 1;
                if (fn & 1) {
                    MMA_F16(acc[fn], a[0], a[1], a[2], a[3], bf[bg][2], bf[bg][3]);
                } else {
                    MMA_F16(acc[fn], a[0], a[1], a[2], a[3], bf[bg][0], bf[bg][1]);
                }
            }
        }

        float mx0 = -1e30f, mx1 = -1e30f;
        if (kt == 0 || kt == NKT - 1) {
            const int qi0 = q0 + r0;
            const int qi1 = qi0 + 8;
            #pragma unroll
            for (int fn = 0; fn < 4; fn++) {
                int c  = wn * 32 + fn * 8 + c2;
                int kj = kb + c;
                #pragma unroll
                for (int jj = 0; jj < 2; jj++) {
                    int k = kj + jj;
                    bool ok0 = (k <= qi0) && (qi0 - k <= MEMW);
                    bool ok1 = (k <= qi1) && (qi1 - k <= MEMW);
                    acc[fn][jj]     = ok0 ? acc[fn][jj]     * SCL : -1e30f;
                    acc[fn][2 + jj] = ok1 ? acc[fn][2 + jj] * SCL : -1e30f;
                    mx0 = fmaxf(mx0, acc[fn][jj]);
                    mx1 = fmaxf(mx1, acc[fn][2 + jj]);
                }
            }
        } else {
            #pragma unroll
            for (int fn = 0; fn < 4; fn++) {
                #pragma unroll
                for (int jj = 0; jj < 2; jj++) {
                    acc[fn][jj]     *= SCL;
                    acc[fn][2 + jj] *= SCL;
                    mx0 = fmaxf(mx0, acc[fn][jj]);
                    mx1 = fmaxf(mx1, acc[fn][2 + jj]);
                }
            }
        }
        mx0 = fmaxf(mx0, __shfl_xor_sync(0xFFFFFFFF, mx0, 1));
        mx0 = fmaxf(mx0, __shfl_xor_sync(0xFFFFFFFF, mx0, 2));
        mx1 = fmaxf(mx1, __shfl_xor_sync(0xFFFFFFFF, mx1, 1));
        mx1 = fmaxf(mx1, __shfl_xor_sync(0xFFFFFFFF, mx1, 2));

        float m0 = fmaxf(m_old0, mx0);
        float m1 = fmaxf(m_old1, mx1);
        float f0 = ex2f(m_old0 - m0);
        float f1 = ex2f(m_old1 - m1);
        m_old0 = m0;
        m_old1 = m1;

        uint32_t aP[2][4];
        float s0 = 0.f, s1 = 0.f;
        #pragma unroll
        for (int kk = 0; kk < 2; kk++) {
            float p00 = ex2f(acc[2*kk][0] - m0);
            float p01 = ex2f(acc[2*kk][1] - m0);
            float p02 = ex2f(acc[2*kk][2] - m1);
            float p03 = ex2f(acc[2*kk][3] - m1);
            float p10 = ex2f(acc[2*kk+1][0] - m0);
            float p11 = ex2f(acc[2*kk+1][1] - m0);
            float p12 = ex2f(acc[2*kk+1][2] - m1);
            float p13 = ex2f(acc[2*kk+1][3] - m1);
            aP[kk][0] = packh2(p00, p01);
            aP[kk][1] = packh2(p02, p03);
            aP[kk][2] = packh2(p10, p11);
            aP[kk][3] = packh2(p12, p13);
            s0 += p00 + p01 + p10 + p11;
            s1 += p02 + p03 + p12 + p13;
        }
        s0 += __shfl_xor_sync(0xFFFFFFFF, s0, 1);
        s0 += __shfl_xor_sync(0xFFFFFFFF, s0, 2);
        s1 += __shfl_xor_sync(0xFFFFFFFF, s1, 1);
        s1 += __shfl_xor_sync(0xFFFFFFFF, s1, 2);
        srun0 = srun0 * f0 + s0;
        srun1 = srun1 * f1 + s1;

        #pragma unroll
        for (int fn = 0; fn < 8; fn++) {
            oacc[fn][0] *= f0;
            oacc[fn][1] *= f0;
            oacc[fn][2] *= f1;
            oacc[fn][3] *= f1;
        }

        #pragma unroll
        for (int kk = 0; kk < 2; kk++) {
            uint32_t bf[4][4];
            #pragma unroll
            for (int g2 = 0; g2 < 4; g2++) {
                int row = wn * 32 + kk * 16 + (lane & 7) + ((lane >> 3) & 1) * 8;
                int bcol = g2 * 32 + (lane >> 4) * 16;
                LDSM_X4T(bf[g2][0], bf[g2][1], bf[g2][2], bf[g2][3],
                         uV + boff + SW128((uint32_t)(row * 128 + bcol)));
            }
            #pragma unroll
            for (int fn = 0; fn < 8; fn++) {
                const int bg = fn >> 1;
                if (fn & 1) {
                    MMA_F16(oacc[fn], aP[kk][0], aP[kk][1], aP[kk][2], aP[kk][3],
                            bf[bg][2], bf[bg][3]);
                } else {
                    MMA_F16(oacc[fn], aP[kk][0], aP[kk][1], aP[kk][2], aP[kk][3],
                            bf[bg][0], bf[bg][1]);
                }
            }
        }
    }

    if (wn == 1) {
        #pragma unroll
        for (int fn = 0; fn < 8; fn++) {
            int col = fn * 8 + c2;
            float* d0 = &Obuf[(size_t)r0 * OBP + col];
            float* d1 = &Obuf[(size_t)(r0 + 8) * OBP + col];
            d0[0] = oacc[fn][0]; d0[1] = oacc[fn][1];
            d1[0] = oacc[fn][2]; d1[1] = oacc[fn][3];
        }
        if ((lane & 3) == 0) {
            Sm[r0] = m_old0;  Sm[r0 + 8] = m_old1;
            Sl[r0] = srun0;   Sl[r0 + 8] = srun1;
        }
    }
    BAR_PAIR(wm + 1);
    if (wn == 0) {
        float mo0 = Sm[r0], mo1 = Sm[r0 + 8];
        float lo0 = Sl[r0], lo1 = Sl[r0 + 8];
        float mm0 = fmaxf(m_old0, mo0);
        float mm1 = fmaxf(m_old1, mo1);
        float as0 = ex2f(m_old0 - mm0), ao0 = ex2f(mo0 - mm0);
        float as1 = ex2f(m_old1 - mm1), ao1 = ex2f(mo1 - mm1);
        float inv0 = 1.0f / (srun0 * as0 + lo0 * ao0);
        float inv1 = 1.0f / (srun1 * as1 + lo1 * ao1);
        #pragma unroll
        for (int fn = 0; fn < 8; fn++) {
            int col = fn * 8 + c2;
            const float* s0p = &Obuf[(size_t)r0 * OBP + col];
            const float* s1p = &Obuf[(size_t)(r0 + 8) * OBP + col];
            __half* p0 = &y[(size_t)(b * TT + q0 + r0) * CC + h * DD + col];
            __half* p1 = &y[(size_t)(b * TT + q0 + r0 + 8) * CC + h * DD + col];
            *(uint32_t*)p0 = packh2((oacc[fn][0] * as0 + s0p[0] * ao0) * inv0,
                                    (oacc[fn][1] * as0 + s0p[1] * ao0) * inv0);
            *(uint32_t*)p1 = packh2((oacc[fn][2] * as1 + s1p[0] * ao1) * inv1,
                                    (oacc[fn][3] * as1 + s1p[1] * ao1) * inv1);
        }
    }
}

// ===========================================================================
// launcher: 2-stream batch pipeline, split convert, per-shape GEMM tiles
// ===========================================================================
extern "C" void kernel_launch(void* const* d_in, const int* in_sizes, int n_in,
                              void* d_out, int out_size) {
    const float* x      = (const float*)d_in[0];
    const float* w_attn = (const float*)d_in[1];
    const float* w_proj = (const float*)d_in[2];
    float* out = (float*)d_out;

    __half *qkv = nullptr, *yb = nullptr, *xc = nullptr, *wac = nullptr, *wpc = nullptr;
    cudaGetSymbolAddress((void**)&qkv, g_qkv);
    cudaGetSymbolAddress((void**)&yb,  g_y);
    cudaGetSymbolAddress((void**)&xc,  g_xc);
    cudaGetSymbolAddress((void**)&wac, g_wac);
    cudaGetSymbolAddress((void**)&wpc, g_wpc);

    cudaFuncSetAttribute(attn_flash,
                         cudaFuncAttributeMaxDynamicSharedMemorySize, ATTN_SMEM_BYTES);
    cudaFuncSetAttribute(gemm_fp16<128>,
                         cudaFuncAttributeMaxDynamicSharedMemorySize, GEMM_SMEM_128);
    cudaFuncSetAttribute(gemm_fp16<64>,
                         cudaFuncAttributeMaxDynamicSharedMemorySize, GEMM_SMEM_64);

    cudaStream_t s1;
    cudaStreamCreateWithFlags(&s1, cudaStreamNonBlocking);
    cudaEvent_t evQ0, evJoin;
    cudaEventCreateWithFlags(&evQ0,  cudaEventDisableTiming);
    cudaEventCreateWithFlags(&evJoin, cudaEventDisableTiming);

    const int MH = M_TOT / 2;

    // 0) split convert: part0 (weights + x[b0]) on s0, part1 (x[b1]) on s1
    convert_kernel<<<(P0_TOTAL8 + 255) / 256, 256, 0, 0>>>(x, w_attn, w_proj, 0);
    convert_kernel<<<(P1_TOTAL8 + 255) / 256, 256, 0, s1>>>(x, w_attn, w_proj, 1);

    // 1a) QKV(b0) on s0 (128x128 tile)
    {
        dim3 grid(QKVN / 128, MH / GBM);
        gemm_fp16<128><<<grid, 256, GEMM_SMEM_128, 0>>>(xc, wac, qkv,
                                                        M_TOT, QKVN, CC, 1, 0);
    }
    cudaEventRecord(evQ0, 0);
    cudaStreamWaitEvent(s1, evQ0, 0);   // stagger: QKV(b1) after QKV(b0)

    // 1b) QKV(b1) on s1
    {
        dim3 grid(QKVN / 128, MH / GBM);
        gemm_fp16<128><<<grid, 256, GEMM_SMEM_128, s1>>>(xc, wac, qkv,
                                                         M_TOT, QKVN, CC, 1, MH);
    }
    // 2a/3a) attn(b0) + proj(b0) on s0 (proj uses 128x64 tile)
    {
        dim3 grid(TT / QT, HH);
        attn_flash<<<grid, 256, ATTN_SMEM_BYTES, 0>>>(qkv, yb, 0);
    }
    {
        dim3 grid(CC / 64, MH / GBM);
        gemm_fp16<64><<<grid, 256, GEMM_SMEM_64, 0>>>(yb, wpc, out,
                                                      M_TOT, CC, CC, 0, 0);
    }
    // 2b/3b) attn(b1) + proj(b1) on s1
    {
        dim3 grid(TT / QT, HH);
        attn_flash<<<grid, 256, ATTN_SMEM_BYTES, s1>>>(qkv, yb, 1);
    }
    {
        dim3 grid(CC / 64, MH / GBM);
        gemm_fp16<64><<<grid, 256, GEMM_SMEM_64, s1>>>(yb, wpc, out,
                                                       M_TOT, CC, CC, 0, MH);
    }

    cudaEventRecord(evJoin, s1);
    cudaStreamWaitEvent(0, evJoin, 0);
}